// round 2
// baseline (speedup 1.0000x reference)
#include <cuda_runtime.h>
#include <cstdint>
#include <cstddef>

// Problem constants
#define SEQ   512
#define BATCH 64
#define INDIM 128
#define HDIM  512

// Phase-2 decomposition: 16 clusters x 8 CTAs. Cluster owns 4 batches,
// CTA owns 64 output rows (n) of Wh, full K=512 resident in SMEM (fp32).
#define CLU    8
#define NPER   64      // Wh rows per CTA
#define BPER   4       // batches per cluster
#define WPITCH 516     // 512 + 4 floats pad -> conflict-free LDS.128 across 32 rows

typedef unsigned long long ull;

// ---------------------------------------------------------------------------
// Packed fp32x2 FMA (sm_103a). ptxas never auto-fuses this; it doubles fp32
// throughput vs 3-reg FFMA (rt_SMSP 2 -> effective 128 FMA lanes/cyc/SM).
// ---------------------------------------------------------------------------
__device__ __forceinline__ void fma2(ull& d, ull a, ull b) {
    asm("fma.rn.f32x2 %0, %1, %2, %0;" : "+l"(d) : "l"(a), "l"(b));
}
__device__ __forceinline__ float2 unpack2(ull v) {
    float2 r; asm("mov.b64 {%0, %1}, %2;" : "=f"(r.x), "=f"(r.y) : "l"(v)); return r;
}
__device__ __forceinline__ uint32_t smem_u32(const void* p) {
    return (uint32_t)__cvta_generic_to_shared(p);
}
__device__ __forceinline__ void cluster_sync_() {
    asm volatile("barrier.cluster.arrive.aligned;" ::: "memory");  // release
    asm volatile("barrier.cluster.wait.aligned;"  ::: "memory");   // acquire
}

// ===========================================================================
// Phase 1: xi[s,b,h] = sum_i x[s,b,i]*Wi[h,i] + bi[h], written IN-PLACE into
// d_out's h_seq region (phase 2 consumes slice t, then overwrites it with h_t).
// Tiled fp32x2 GEMM: M=SEQ*B=32768, N=H=512, K=IN=128 (K fits in one tile).
// Block: 256 threads -> 64x64 tile, 4x4 outputs/thread (as 4x2 f32x2 accums).
// ===========================================================================
extern "C" __global__ void __launch_bounds__(256, 1)
rnn_phase1(const float* __restrict__ x, const float* __restrict__ Wi,
           const float* __restrict__ bi, float* __restrict__ out)
{
    extern __shared__ char smemraw[];
    float2* xs2 = (float2*)smemraw;                     // [128][64], value duplicated (lo==hi)
    float*  ws  = (float*)(smemraw + INDIM * 64 * 8);   // [128][64]

    const int tid = threadIdx.x;
    const int m0 = blockIdx.x * 64;   // 512 blocks over s*b rows
    const int nb = blockIdx.y * 64;   // 8 blocks over h

    // --- Load tiles transposed (k-major) ---
    const int lm = tid & 63;
    const int kc = (tid >> 6) * 32;
    const float* xrow = x  + (size_t)(m0 + lm) * INDIM + kc;
    const float* wrow = Wi + (size_t)(nb + lm) * INDIM + kc;
    #pragma unroll
    for (int kk = 0; kk < 32; kk += 4) {
        float4 v = *(const float4*)(xrow + kk);
        xs2[(kc+kk+0)*64 + lm] = make_float2(v.x, v.x);
        xs2[(kc+kk+1)*64 + lm] = make_float2(v.y, v.y);
        xs2[(kc+kk+2)*64 + lm] = make_float2(v.z, v.z);
        xs2[(kc+kk+3)*64 + lm] = make_float2(v.w, v.w);
        float4 w = *(const float4*)(wrow + kk);
        ws[(kc+kk+0)*64 + lm] = w.x;
        ws[(kc+kk+1)*64 + lm] = w.y;
        ws[(kc+kk+2)*64 + lm] = w.z;
        ws[(kc+kk+3)*64 + lm] = w.w;
    }
    __syncthreads();

    const int tx = tid & 15, ty = tid >> 4;
    ull c00=0,c01=0,c10=0,c11=0,c20=0,c21=0,c30=0,c31=0;
    const ull*   xa = (const ull*)xs2 + ty * 4;     // duplicated-pair a operands
    const float* wb = ws + tx * 4;
    #pragma unroll 8
    for (int k = 0; k < INDIM; ++k) {
        ulonglong2 bb = *(const ulonglong2*)(wb + k * 64);
        ull a0 = xa[k*64 + 0]; fma2(c00, a0, bb.x); fma2(c01, a0, bb.y);
        ull a1 = xa[k*64 + 1]; fma2(c10, a1, bb.x); fma2(c11, a1, bb.y);
        ull a2 = xa[k*64 + 2]; fma2(c20, a2, bb.x); fma2(c21, a2, bb.y);
        ull a3 = xa[k*64 + 3]; fma2(c30, a3, bb.x); fma2(c31, a3, bb.y);
    }

    float4 bv = *(const float4*)(bi + nb + tx * 4);
    float* orow = out + (size_t)(m0 + ty * 4) * HDIM + nb + tx * 4;
    {
        float2 l, h;
        l = unpack2(c00); h = unpack2(c01);
        *(float4*)(orow + 0*HDIM) = make_float4(l.x+bv.x, l.y+bv.y, h.x+bv.z, h.y+bv.w);
        l = unpack2(c10); h = unpack2(c11);
        *(float4*)(orow + 1*HDIM) = make_float4(l.x+bv.x, l.y+bv.y, h.x+bv.z, h.y+bv.w);
        l = unpack2(c20); h = unpack2(c21);
        *(float4*)(orow + 2*HDIM) = make_float4(l.x+bv.x, l.y+bv.y, h.x+bv.z, h.y+bv.w);
        l = unpack2(c30); h = unpack2(c31);
        *(float4*)(orow + 3*HDIM) = make_float4(l.x+bv.x, l.y+bv.y, h.x+bv.z, h.y+bv.w);
    }
}

// ===========================================================================
// Phase 2: persistent per-cluster recurrence.
// Grid: 128 CTAs, __cluster_dims__(8). Cluster c -> batches 4c..4c+3.
// CTA rank r -> output rows [64r, 64r+64). Wh slice fp32 in SMEM (padded).
// Thread map: 256 threads = (nl in [0,64)) x (kq in [0,4)); each thread does a
// 128-long partial dot for 4 batches with f32x2, kq-reduced via SMEM.
// h exchanged per step by DSMEM push (mapa + st.shared::cluster) into a
// double-buffered h array; ONE cluster.sync per step (release/acquire).
// ===========================================================================
extern "C" __global__ void __cluster_dims__(CLU, 1, 1) __launch_bounds__(256, 1)
rnn_phase2(const float* __restrict__ Wh, const float* __restrict__ bh,
           float* __restrict__ out, float* __restrict__ out_last)
{
    extern __shared__ char smemraw2[];
    float*  Wsh = (float*)smemraw2;                    // [64][516]  = 129 KB
    float*  hb  = Wsh + NPER * WPITCH;                 // [2][4][512] = 16 KB (double buffer)
    float4* red = (float4*)(hb + 2 * BPER * HDIM);     // [4][64] of (b0,b1,b2,b3) = 4 KB

    const int tid = threadIdx.x;
    uint32_t rank; asm("mov.u32 %0, %%cluster_ctarank;" : "=r"(rank));
    const int cl  = blockIdx.x / CLU;     // cluster id 0..15
    const int n0  = (int)rank * NPER;
    const int gb0 = cl * BPER;

    // Load my Wh slice (coalesced along k), padded rows for conflict-free LDS.128
    for (int idx = tid; idx < NPER * (HDIM / 4); idx += 256) {
        int n  = idx >> 7;          // / 128
        int k4 = idx & 127;
        float4 v = *(const float4*)(Wh + (size_t)(n0 + n) * HDIM + k4 * 4);
        *(float4*)(Wsh + n * WPITCH + k4 * 4) = v;
    }
    for (int idx = tid; idx < 2 * BPER * HDIM; idx += 256) hb[idx] = 0.0f;  // h0 = 0
    __syncthreads();
    cluster_sync_();   // all peers initialized before any DSMEM traffic

    const int nl = tid & 63;
    const int kq = tid >> 6;
    const int k0 = kq * 128;
    const float bias = bh[n0 + nl];

    for (int t = 0; t < SEQ; ++t) {
        const int pr = t & 1;
        const float* hp = hb + pr * (BPER * HDIM) + k0;       // read buffer
        float*       hw = hb + (pr ^ 1) * (BPER * HDIM);      // write buffer

        // Prefetch xi (and the output address) early — L2 latency hidden under dot
        float xi0 = 0.f, xi1 = 0.f, xi2 = 0.f, xi3 = 0.f;
        const size_t obase = ((size_t)t * BATCH + gb0) * HDIM + n0 + nl;
        if (kq == 0) {
            xi0 = out[obase];
            xi1 = out[obase +     HDIM];
            xi2 = out[obase + 2 * HDIM];
            xi3 = out[obase + 3 * HDIM];
        }

        // 128-long partial dot, 4 batches, packed fp32x2 (8 independent accums)
        ull aA0=0,aA1=0,aA2=0,aA3=0,aB0=0,aB1=0,aB2=0,aB3=0;
        const ulonglong2* wr = (const ulonglong2*)(Wsh + nl * WPITCH + k0);
        const ulonglong2* h0p = (const ulonglong2*)(hp);
        const ulonglong2* h1p = (const ulonglong2*)(hp +     HDIM);
        const ulonglong2* h2p = (const ulonglong2*)(hp + 2 * HDIM);
        const ulonglong2* h3p = (const ulonglong2*)(hp + 3 * HDIM);
        #pragma unroll 8
        for (int c = 0; c < 32; ++c) {
            ulonglong2 w  = wr[c];
            ulonglong2 v0 = h0p[c]; fma2(aA0, w.x, v0.x); fma2(aB0, w.y, v0.y);
            ulonglong2 v1 = h1p[c]; fma2(aA1, w.x, v1.x); fma2(aB1, w.y, v1.y);
            ulonglong2 v2 = h2p[c]; fma2(aA2, w.x, v2.x); fma2(aB2, w.y, v2.y);
            ulonglong2 v3 = h3p[c]; fma2(aA3, w.x, v3.x); fma2(aB3, w.y, v3.y);
        }
        float2 p, q; float s0, s1, s2, s3;
        p = unpack2(aA0); q = unpack2(aB0); s0 = (p.x + q.x) + (p.y + q.y);
        p = unpack2(aA1); q = unpack2(aB1); s1 = (p.x + q.x) + (p.y + q.y);
        p = unpack2(aA2); q = unpack2(aB2); s2 = (p.x + q.x) + (p.y + q.y);
        p = unpack2(aA3); q = unpack2(aB3); s3 = (p.x + q.x) + (p.y + q.y);
        red[kq * 64 + nl] = make_float4(s0, s1, s2, s3);
        __syncthreads();

        if (kq == 0) {
            float4 r0 = red[nl], r1 = red[64 + nl], r2 = red[128 + nl], r3 = red[192 + nl];
            float v0 = tanhf(r0.x + r1.x + r2.x + r3.x + bias + xi0);
            float v1 = tanhf(r0.y + r1.y + r2.y + r3.y + bias + xi1);
            float v2 = tanhf(r0.z + r1.z + r2.z + r3.z + bias + xi2);
            float v3 = tanhf(r0.w + r1.w + r2.w + r3.w + bias + xi3);

            // h_seq output (overwrites consumed xi slice in-place)
            out[obase]            = v0;
            out[obase +     HDIM] = v1;
            out[obase + 2 * HDIM] = v2;
            out[obase + 3 * HDIM] = v3;
            if (t == SEQ - 1 && out_last) {
                size_t lb = (size_t)gb0 * HDIM + n0 + nl;
                out_last[lb]            = v0;
                out_last[lb +     HDIM] = v1;
                out_last[lb + 2 * HDIM] = v2;
                out_last[lb + 3 * HDIM] = v3;
            }

            // DSMEM push-broadcast my h slice into all 8 CTAs' write buffer
            uint32_t la = smem_u32(hw + n0 + nl);   // b=0 element; b stride = 2048 B
            #pragma unroll
            for (uint32_t r = 0; r < CLU; ++r) {
                uint32_t ra;
                asm volatile("mapa.shared::cluster.u32 %0, %1, %2;" : "=r"(ra) : "r"(la), "r"(r));
                asm volatile("st.shared::cluster.f32 [%0], %1;" :: "r"(ra),         "f"(v0) : "memory");
                asm volatile("st.shared::cluster.f32 [%0], %1;" :: "r"(ra + 2048u), "f"(v1) : "memory");
                asm volatile("st.shared::cluster.f32 [%0], %1;" :: "r"(ra + 4096u), "f"(v2) : "memory");
                asm volatile("st.shared::cluster.f32 [%0], %1;" :: "r"(ra + 6144u), "f"(v3) : "memory");
            }
        }
        // Release my writes / acquire peers' writes; also fences the double buffer.
        cluster_sync_();
    }
}

// ===========================================================================
// Launch
// ===========================================================================
extern "C" void kernel_launch(void* const* d_in, const int* in_sizes, int n_in,
                              void* d_out, int out_size) {
    (void)in_sizes; (void)n_in;
    const float* x  = (const float*)d_in[0];
    const float* Wi = (const float*)d_in[1];
    const float* bi = (const float*)d_in[2];
    const float* Wh = (const float*)d_in[3];
    const float* bh = (const float*)d_in[4];
    float* out = (float*)d_out;

    const long long SBH = (long long)SEQ * BATCH * HDIM;
    float* out_last = ((long long)out_size >= SBH + (long long)BATCH * HDIM)
                          ? out + SBH : nullptr;

    const int P1_SMEM = INDIM * 64 * 8 + INDIM * 64 * 4;                       // 96 KB
    const int P2_SMEM = (NPER * WPITCH + 2 * BPER * HDIM + 4 * 64 * 4) * 4;    // ~149 KB

    cudaFuncSetAttribute(rnn_phase1, cudaFuncAttributeMaxDynamicSharedMemorySize, P1_SMEM);
    cudaFuncSetAttribute(rnn_phase2, cudaFuncAttributeMaxDynamicSharedMemorySize, P2_SMEM);

    rnn_phase1<<<dim3(512, 8, 1), 256, P1_SMEM>>>(x, Wi, bi, out);
    rnn_phase2<<<(BATCH / BPER) * CLU, 256, P2_SMEM>>>(Wh, bh, out, out_last);
}